// round 16
// baseline (speedup 1.0000x reference)
#include <cuda_runtime.h>
#include <cuda_bf16.h>
#include <cstdint>

// ---------------- problem constants ------------------------------------
#define N_NODES  100000
#define F_IN     128
#define HID      64
#define N_EDGES  1600000
#define N_GRAPHS 1000
#define PER_G    100
#define TOPK     30
#define KSZ      3
#define CONV_O   32
#define CONV_T   28
#define FLAT     896
#define G_PER_BLK 4
#define M_TILES  782              // ceil(100000/128)
#define SCAN_B   1024
#define NB_SCAN  98

// smem (floats): A planes [2][128][36], B planes [2][32][136]
#define A_PL 4608
#define B_PL 4352
#define GEMM_FLOATS (2*A_PL + 2*B_PL)          // 17920

// ---------------- tf32 helpers ------------------------------------------
__device__ __forceinline__ void split_tf32(float v, uint32_t& t1, uint32_t& t2) {
    asm("cvt.rna.tf32.f32 %0, %1;" : "=r"(t1) : "f"(v));
    float r = v - __uint_as_float(t1);
    asm("cvt.rna.tf32.f32 %0, %1;" : "=r"(t2) : "f"(r));
}
#define MMA_TF32(d, a, b) \
    asm volatile("mma.sync.aligned.m16n8k8.row.col.f32.tf32.tf32.f32 " \
        "{%0,%1,%2,%3}, {%4,%5,%6,%7}, {%8,%9}, {%0,%1,%2,%3};" \
        : "+f"((d)[0]), "+f"((d)[1]), "+f"((d)[2]), "+f"((d)[3]) \
        : "r"((a)[0]), "r"((a)[1]), "r"((a)[2]), "r"((a)[3]), \
          "r"((b)[0]), "r"((b)[1]))

// ---------------- scratch ----------------------------------------------
__device__ int   g_deg[N_NODES];
__device__ int   g_off[N_NODES];
__device__ int   g_cur[N_NODES];
__device__ int   g_bsum[NB_SCAN];
__device__ int   g_csr[N_EDGES];
__device__ float g_TS[(size_t)N_NODES * 128];    // T | S
__device__ float g_h[(size_t)N_NODES * 64];
__device__ float g_topk[(size_t)N_GRAPHS * TOPK * HID];
__device__ float g_Bimg[65536];                  // tf32 B planes

// ---------------- init: zero deg + tf32 B images ------------------------
__global__ void k_init(const float* __restrict__ Wl1, const float* __restrict__ Wr1,
                       const float* __restrict__ Wl2, const float* __restrict__ Wr2,
                       const float* __restrict__ Wl3, const float* __restrict__ Wr3) {
    int i = blockIdx.x * blockDim.x + threadIdx.x;
    if (i < N_NODES) g_deg[i] = 0;
    if (i < 32768) {
        const float *Wl, *Wr; int base, K, rem = i;
        if (i < 16384)      { Wl = Wl1; Wr = Wr1; base = 0;     K = 128; }
        else if (i < 24576) { Wl = Wl2; Wr = Wr2; base = 32768; K = 64;  rem = i - 16384; }
        else                { Wl = Wl3; Wr = Wr3; base = 49152; K = 64;  rem = i - 24576; }
        int k = rem >> 7, n = rem & 127;
        float v = (n < 64) ? Wl[k * 64 + n] : Wr[k * 64 + (n - 64)];
        uint32_t t1, t2;
        split_tf32(v, t1, t2);
        g_Bimg[base + k * 128 + n]           = __uint_as_float(t1);
        g_Bimg[base + K * 128 + k * 128 + n] = __uint_as_float(t2);
    }
}

__global__ void k_count(const int* __restrict__ dst) {
    int e = blockIdx.x * blockDim.x + threadIdx.x;
    if (e < N_EDGES) atomicAdd(&g_deg[dst[e]], 1);
}

// ---------------- 3-kernel scan (R11-proven) ----------------------------
__global__ void k_scan1() {
    __shared__ int s[SCAN_B];
    int i = blockIdx.x * SCAN_B + threadIdx.x;
    int v = (i < N_NODES) ? g_deg[i] : 0;
    s[threadIdx.x] = v;
    __syncthreads();
    for (int d = 1; d < SCAN_B; d <<= 1) {
        int t = (threadIdx.x >= d) ? s[threadIdx.x - d] : 0;
        __syncthreads();
        s[threadIdx.x] += t;
        __syncthreads();
    }
    if (i < N_NODES) g_off[i] = s[threadIdx.x] - v;
    if (threadIdx.x == SCAN_B - 1) g_bsum[blockIdx.x] = s[SCAN_B - 1];
}
__global__ void k_scan2() {
    if (threadIdx.x == 0 && blockIdx.x == 0) {
        int acc = 0;
        for (int b = 0; b < NB_SCAN; ++b) { int t = g_bsum[b]; g_bsum[b] = acc; acc += t; }
    }
}
__global__ void k_scan3() {
    int i = blockIdx.x * blockDim.x + threadIdx.x;
    if (i < N_NODES) {
        int o = g_off[i] + g_bsum[i >> 10];
        g_off[i] = o;
        g_cur[i] = o;
    }
}
__global__ void k_fill_csr(const int* __restrict__ src, const int* __restrict__ dst) {
    int e = blockIdx.x * blockDim.x + threadIdx.x;
    if (e < N_EDGES) {
        int pos = atomicAdd(&g_cur[dst[e]], 1);
        g_csr[pos] = src[e];
    }
}

// ---------------- 3xTF32 mma.sync GEMM: 512 threads, warp tile 32x32 ----
template<int K>
__global__ void __launch_bounds__(512) k_mma_gemm(
    const float* __restrict__ A, const float* __restrict__ Bg,
    float* __restrict__ T, float* __restrict__ S) {
    extern __shared__ float sm[];
    float* As = sm;                    // [2][128][36]
    float* Bs = sm + 2 * A_PL;         // [2][32][136]
    const int tid = threadIdx.x, lane = tid & 31, wid = tid >> 5;
    const int m0 = blockIdx.x * 128;
    const int warp_m = (wid & 3) * 32;     // 0,32,64,96
    const int warp_n = (wid >> 2) * 32;    // 0,32,64,96
    const int gi = lane >> 2, ti = lane & 3;

    float acc[2][4][4];
#pragma unroll
    for (int mt = 0; mt < 2; ++mt)
#pragma unroll
        for (int nt = 0; nt < 4; ++nt)
#pragma unroll
            for (int c = 0; c < 4; ++c) acc[mt][nt][c] = 0.f;

    for (int k0 = 0; k0 < K; k0 += 32) {
        // ---- stage A: 128 rows x 32 k -> 2 tf32 planes (1024 float4 / 512 thr)
#pragma unroll
        for (int it = 0; it < 2; ++it) {
            int idx = it * 512 + tid;
            int row = idx >> 3, kq = (idx & 7) << 2;
            int grow = m0 + row;
            float4 v = (grow < N_NODES)
                ? *reinterpret_cast<const float4*>(A + (size_t)grow * K + k0 + kq)
                : make_float4(0.f, 0.f, 0.f, 0.f);
            uint32_t h1[4], h2[4];
            split_tf32(v.x, h1[0], h2[0]);
            split_tf32(v.y, h1[1], h2[1]);
            split_tf32(v.z, h1[2], h2[2]);
            split_tf32(v.w, h1[3], h2[3]);
            float* p0 = As + row * 36 + kq;
            *reinterpret_cast<float4*>(p0) = make_float4(
                __uint_as_float(h1[0]), __uint_as_float(h1[1]),
                __uint_as_float(h1[2]), __uint_as_float(h1[3]));
            *reinterpret_cast<float4*>(p0 + A_PL) = make_float4(
                __uint_as_float(h2[0]), __uint_as_float(h2[1]),
                __uint_as_float(h2[2]), __uint_as_float(h2[3]));
        }
        // ---- stage B: 2 planes x 32 k x 128 n (2048 float4 / 512 thr)
#pragma unroll
        for (int it = 0; it < 4; ++it) {
            int idx = it * 512 + tid;
            int pl = idx >> 10, rem = idx & 1023;
            int kk = rem >> 5, nq = (rem & 31) << 2;
            float4 v = *reinterpret_cast<const float4*>(
                Bg + (size_t)pl * (K * 128) + (size_t)(k0 + kk) * 128 + nq);
            *reinterpret_cast<float4*>(Bs + pl * B_PL + kk * 136 + nq) = v;
        }
        __syncthreads();

#pragma unroll
        for (int ks = 0; ks < 4; ++ks) {
            uint32_t af[2][2][4];
#pragma unroll
            for (int mt = 0; mt < 2; ++mt)
#pragma unroll
                for (int pl = 0; pl < 2; ++pl) {
                    const float* b = As + pl * A_PL + (warp_m + mt * 16 + gi) * 36 + ks * 8 + ti;
                    af[mt][pl][0] = __float_as_uint(b[0]);
                    af[mt][pl][1] = __float_as_uint(b[8 * 36]);
                    af[mt][pl][2] = __float_as_uint(b[4]);
                    af[mt][pl][3] = __float_as_uint(b[8 * 36 + 4]);
                }
            uint32_t bf[4][2][2];
#pragma unroll
            for (int nt = 0; nt < 4; ++nt)
#pragma unroll
                for (int pl = 0; pl < 2; ++pl) {
                    const float* b = Bs + pl * B_PL + (ks * 8 + ti) * 136 + warp_n + nt * 8 + gi;
                    bf[nt][pl][0] = __float_as_uint(b[0]);
                    bf[nt][pl][1] = __float_as_uint(b[4 * 136]);
                }
#pragma unroll
            for (int mt = 0; mt < 2; ++mt)
#pragma unroll
                for (int nt = 0; nt < 4; ++nt) {
                    MMA_TF32(acc[mt][nt], af[mt][1], bf[nt][0]);   // A2*B1
                    MMA_TF32(acc[mt][nt], af[mt][0], bf[nt][1]);   // A1*B2
                    MMA_TF32(acc[mt][nt], af[mt][0], bf[nt][0]);   // A1*B1
                }
        }
        __syncthreads();
    }

    float* O = (warp_n < 64) ? T : S;
    const int nbase = warp_n & 63;
#pragma unroll
    for (int mt = 0; mt < 2; ++mt) {
        int row0 = m0 + warp_m + mt * 16 + gi;
#pragma unroll
        for (int nt = 0; nt < 4; ++nt) {
            int col = nbase + nt * 8 + 2 * ti;
            if (row0 < N_NODES)
                *reinterpret_cast<float2*>(O + (size_t)row0 * 64 + col) =
                    make_float2(acc[mt][nt][0], acc[mt][nt][1]);
            if (row0 + 8 < N_NODES)
                *reinterpret_cast<float2*>(O + (size_t)(row0 + 8) * 64 + col) =
                    make_float2(acc[mt][nt][2], acc[mt][nt][3]);
        }
    }
}

// ---------------- fused aggregate + epilogue (high occupancy) -----------
__global__ void __launch_bounds__(256) k_aggfuse(
    const float* __restrict__ T, const float* __restrict__ S,
    const float* __restrict__ bias, float* __restrict__ out) {
    int node = (blockIdx.x * blockDim.x + threadIdx.x) >> 5;
    int lane = threadIdx.x & 31;
    if (node >= N_NODES) return;
    int beg = g_off[node];
    int end = beg + g_deg[node];
    float2 acc = make_float2(0.f, 0.f);
    int e = beg;
    for (; e + 4 <= end; e += 4) {
        int s0 = g_csr[e], s1 = g_csr[e + 1], s2 = g_csr[e + 2], s3 = g_csr[e + 3];
        float2 v0 = *reinterpret_cast<const float2*>(T + (size_t)s0 * 64 + 2 * lane);
        float2 v1 = *reinterpret_cast<const float2*>(T + (size_t)s1 * 64 + 2 * lane);
        float2 v2 = *reinterpret_cast<const float2*>(T + (size_t)s2 * 64 + 2 * lane);
        float2 v3 = *reinterpret_cast<const float2*>(T + (size_t)s3 * 64 + 2 * lane);
        acc.x += v0.x; acc.y += v0.y;
        acc.x += v1.x; acc.y += v1.y;
        acc.x += v2.x; acc.y += v2.y;
        acc.x += v3.x; acc.y += v3.y;
    }
    for (; e < end; ++e) {
        float2 v = *reinterpret_cast<const float2*>(T + (size_t)g_csr[e] * 64 + 2 * lane);
        acc.x += v.x; acc.y += v.y;
    }
    int d = end - beg;
    float inv = 1.f / (float)(d > 0 ? d : 1);
    float2 sv = *reinterpret_cast<const float2*>(S + (size_t)node * 64 + 2 * lane);
    float2 bv = *reinterpret_cast<const float2*>(bias + 2 * lane);
    float2 r;
    r.x = acc.x * inv + sv.x + bv.x;  r.x = r.x > 0.f ? r.x : 0.f;
    r.y = acc.y * inv + sv.y + bv.y;  r.y = r.y > 0.f ? r.y : 0.f;
    *reinterpret_cast<float2*>(out + (size_t)node * 64 + 2 * lane) = r;
}

// ---------------- sort-pool (R11-proven) --------------------------------
__global__ void __launch_bounds__(128) k_sortpool(const float* __restrict__ h) {
    int g = blockIdx.x;
    __shared__ float key[PER_G];
    __shared__ int   sel[TOPK];
    int t = threadIdx.x;
    if (t < PER_G) key[t] = h[((size_t)(g * PER_G + t)) * HID + (HID - 1)];
    __syncthreads();
    if (t < PER_G) {
        float ki = key[t];
        int r = 0;
#pragma unroll 4
        for (int j = 0; j < PER_G; ++j) {
            float kj = key[j];
            r += (kj > ki) || (kj == ki && j < t);
        }
        if (r < TOPK) sel[r] = t;
    }
    __syncthreads();
    for (int idx = t; idx < TOPK * HID; idx += 128) {
        int slot = idx >> 6, f = idx & 63;
        g_topk[(size_t)g * (TOPK * HID) + idx] =
            h[((size_t)(g * PER_G + sel[slot])) * HID + f];
    }
}

// ---------------- conv1d + MLP head: 4 graphs per block -----------------
__global__ void __launch_bounds__(256) k_head(
    const float* __restrict__ cw, const float* __restrict__ cb,
    const float* __restrict__ w1, const float* __restrict__ bb1,
    const float* __restrict__ w2, const float* __restrict__ bb2,
    float* __restrict__ out) {
    int g0 = blockIdx.x * G_PER_BLK, tid = threadIdx.x;
    __shared__ float cws[CONV_O * HID * KSZ];
    __shared__ float tk[G_PER_BLK][TOPK * HID];
    __shared__ float yf[G_PER_BLK][FLAT];
    __shared__ float z[G_PER_BLK][HID];

    for (int i = tid; i < CONV_O * HID * KSZ; i += 256) cws[i] = cw[i];
    for (int i = tid; i < G_PER_BLK * TOPK * HID; i += 256) {
        int gl = i / (TOPK * HID), r = i % (TOPK * HID);
        tk[gl][r] = g_topk[(size_t)(g0 + gl) * (TOPK * HID) + r];
    }
    __syncthreads();

    for (int idx = tid; idx < G_PER_BLK * FLAT; idx += 256) {
        int gl = idx / FLAT, rem = idx % FLAT;
        int o = rem / CONV_T, t = rem % CONV_T;
        float acc = __ldg(cb + o);
        const float* cwo = cws + o * (HID * KSZ);
#pragma unroll 8
        for (int i = 0; i < HID; ++i) {
            const float* cwp = cwo + i * KSZ;
            acc += tk[gl][(t + 0) * HID + i] * cwp[0];
            acc += tk[gl][(t + 1) * HID + i] * cwp[1];
            acc += tk[gl][(t + 2) * HID + i] * cwp[2];
        }
        yf[gl][rem] = acc > 0.f ? acc : 0.f;
    }
    __syncthreads();

    {
        int gl = tid >> 6, hh = tid & 63;
        float acc = 0.f;
        for (int f = 0; f < FLAT; ++f)
            acc += yf[gl][f] * __ldg(w1 + (size_t)f * 64 + hh);
        float v = acc + __ldg(bb1 + hh);
        z[gl][hh] = v > 0.f ? v : 0.f;
    }
    __syncthreads();

    if (tid < G_PER_BLK) {
        float s = __ldg(bb2);
#pragma unroll
        for (int h = 0; h < HID; ++h) s += z[tid][h] * __ldg(w2 + h);
        out[g0 + tid] = s;
    }
}

// ---------------- launch ------------------------------------------------
extern "C" void kernel_launch(void* const* d_in, const int* in_sizes, int n_in,
                              void* d_out, int out_size) {
    const float* x   = (const float*)d_in[0];
    const int*   src = (const int*)d_in[1];
    const int*   dst = (const int*)d_in[2];
    const float* wl1 = (const float*)d_in[4];
    const float* wr1 = (const float*)d_in[5];
    const float* b1  = (const float*)d_in[6];
    const float* wl2 = (const float*)d_in[7];
    const float* wr2 = (const float*)d_in[8];
    const float* b2  = (const float*)d_in[9];
    const float* wl3 = (const float*)d_in[10];
    const float* wr3 = (const float*)d_in[11];
    const float* b3  = (const float*)d_in[12];
    const float* cw  = (const float*)d_in[13];
    const float* cb  = (const float*)d_in[14];
    const float* w1  = (const float*)d_in[15];
    const float* bb1 = (const float*)d_in[16];
    const float* w2  = (const float*)d_in[17];
    const float* bb2 = (const float*)d_in[18];
    float* out = (float*)d_out;

    float *p_TS, *p_h, *p_W;
    cudaGetSymbolAddress((void**)&p_TS, g_TS);
    cudaGetSymbolAddress((void**)&p_h,  g_h);
    cudaGetSymbolAddress((void**)&p_W,  g_Bimg);
    float* p_T = p_TS;
    float* p_S = p_TS + (size_t)N_NODES * 64;

    const int GEMM_SZ = GEMM_FLOATS * 4;   // 71680
    cudaFuncSetAttribute(k_mma_gemm<128>, cudaFuncAttributeMaxDynamicSharedMemorySize, GEMM_SZ);
    cudaFuncSetAttribute(k_mma_gemm<64>,  cudaFuncAttributeMaxDynamicSharedMemorySize, GEMM_SZ);

    const int aggBlocks = (N_NODES * 32 + 255) / 256;

    // 0: init   1: count   2: scan1
    k_init<<<(N_NODES + 255) / 256, 256>>>(wl1, wr1, wl2, wr2, wl3, wr3);
    k_count<<<(N_EDGES + 255) / 256, 256>>>(dst);
    k_scan1<<<NB_SCAN, SCAN_B>>>();
    // 3: layer-1 GEMM (K=128) — placed here so the ncu window (-s 5 incl.
    //    ~2 harness launches) lands on it; independent of scan2/3/fill.
    k_mma_gemm<128><<<M_TILES, 512, GEMM_SZ>>>(x, p_W, p_T, p_S);
    // 4-6: finish CSR
    k_scan2<<<1, 32>>>();
    k_scan3<<<(N_NODES + 255) / 256, 256>>>();
    k_fill_csr<<<(N_EDGES + 255) / 256, 256>>>(src, dst);
    // 7: agg1   8: gemm2   9: agg2   10: gemm3   11: agg3
    k_aggfuse<<<aggBlocks, 256>>>(p_T, p_S, b1, p_h);
    k_mma_gemm<64><<<M_TILES, 512, GEMM_SZ>>>(p_h, p_W + 32768, p_T, p_S);
    k_aggfuse<<<aggBlocks, 256>>>(p_T, p_S, b2, p_h);
    k_mma_gemm<64><<<M_TILES, 512, GEMM_SZ>>>(p_h, p_W + 49152, p_T, p_S);
    k_aggfuse<<<aggBlocks, 256>>>(p_T, p_S, b3, p_h);
    // 12: sort-pool   13: head
    k_sortpool<<<N_GRAPHS, 128>>>(p_h);
    k_head<<<N_GRAPHS / G_PER_BLK, 256>>>(cw, cb, w1, bb1, w2, bb2, out);
}

// round 17
// speedup vs baseline: 1.5334x; 1.5334x over previous
#include <cuda_runtime.h>
#include <cuda_bf16.h>
#include <cstdint>

// ---------------- problem constants ------------------------------------
#define N_NODES  100000
#define F_IN     128
#define HID      64
#define N_EDGES  1600000
#define N_GRAPHS 1000
#define PER_G    100
#define TOPK     30
#define KSZ      3
#define CONV_O   32
#define CONV_T   28
#define FLAT     896
#define G_PER_BLK 4
#define M_TILES  782              // ceil(100000/128)
#define SCAN_B   1024
#define NB_SCAN  98

// smem (floats): A planes [2][128][36], B planes [2][32][136]
#define A_PL 4608
#define B_PL 4352
#define GEMM_FLOATS (2*A_PL + 2*B_PL)          // 17920

// ---------------- tf32 helpers ------------------------------------------
__device__ __forceinline__ void split_tf32(float v, uint32_t& t1, uint32_t& t2) {
    asm("cvt.rna.tf32.f32 %0, %1;" : "=r"(t1) : "f"(v));
    float r = v - __uint_as_float(t1);
    asm("cvt.rna.tf32.f32 %0, %1;" : "=r"(t2) : "f"(r));
}
#define MMA_TF32(d, a, b) \
    asm volatile("mma.sync.aligned.m16n8k8.row.col.f32.tf32.tf32.f32 " \
        "{%0,%1,%2,%3}, {%4,%5,%6,%7}, {%8,%9}, {%0,%1,%2,%3};" \
        : "+f"((d)[0]), "+f"((d)[1]), "+f"((d)[2]), "+f"((d)[3]) \
        : "r"((a)[0]), "r"((a)[1]), "r"((a)[2]), "r"((a)[3]), \
          "r"((b)[0]), "r"((b)[1]))

// ---------------- scratch ----------------------------------------------
__device__ int   g_deg[N_NODES];
__device__ int   g_off[N_NODES];
__device__ int   g_cur[N_NODES];
__device__ int   g_bsum[NB_SCAN];
__device__ int   g_csr[N_EDGES];
__device__ float g_TS[(size_t)N_NODES * 128];    // T | S
__device__ float g_h[(size_t)N_NODES * 64];
__device__ float g_topk[(size_t)N_GRAPHS * TOPK * HID];
__device__ float g_Bimg[65536];                  // tf32 B planes

// ---------------- init: zero deg + tf32 B images ------------------------
__global__ void k_init(const float* __restrict__ Wl1, const float* __restrict__ Wr1,
                       const float* __restrict__ Wl2, const float* __restrict__ Wr2,
                       const float* __restrict__ Wl3, const float* __restrict__ Wr3) {
    int i = blockIdx.x * blockDim.x + threadIdx.x;
    if (i < N_NODES) g_deg[i] = 0;
    if (i < 32768) {
        const float *Wl, *Wr; int base, K, rem = i;
        if (i < 16384)      { Wl = Wl1; Wr = Wr1; base = 0;     K = 128; }
        else if (i < 24576) { Wl = Wl2; Wr = Wr2; base = 32768; K = 64;  rem = i - 16384; }
        else                { Wl = Wl3; Wr = Wr3; base = 49152; K = 64;  rem = i - 24576; }
        int k = rem >> 7, n = rem & 127;
        float v = (n < 64) ? Wl[k * 64 + n] : Wr[k * 64 + (n - 64)];
        uint32_t t1, t2;
        split_tf32(v, t1, t2);
        g_Bimg[base + k * 128 + n]           = __uint_as_float(t1);
        g_Bimg[base + K * 128 + k * 128 + n] = __uint_as_float(t2);
    }
}

__global__ void k_count(const int* __restrict__ dst) {
    int e = blockIdx.x * blockDim.x + threadIdx.x;
    if (e < N_EDGES) atomicAdd(&g_deg[dst[e]], 1);
}

// ---------------- 3-kernel scan (R11-proven) ----------------------------
__global__ void k_scan1() {
    __shared__ int s[SCAN_B];
    int i = blockIdx.x * SCAN_B + threadIdx.x;
    int v = (i < N_NODES) ? g_deg[i] : 0;
    s[threadIdx.x] = v;
    __syncthreads();
    for (int d = 1; d < SCAN_B; d <<= 1) {
        int t = (threadIdx.x >= d) ? s[threadIdx.x - d] : 0;
        __syncthreads();
        s[threadIdx.x] += t;
        __syncthreads();
    }
    if (i < N_NODES) g_off[i] = s[threadIdx.x] - v;
    if (threadIdx.x == SCAN_B - 1) g_bsum[blockIdx.x] = s[SCAN_B - 1];
}
__global__ void k_scan2() {
    if (threadIdx.x == 0 && blockIdx.x == 0) {
        int acc = 0;
        for (int b = 0; b < NB_SCAN; ++b) { int t = g_bsum[b]; g_bsum[b] = acc; acc += t; }
    }
}
__global__ void k_scan3() {
    int i = blockIdx.x * blockDim.x + threadIdx.x;
    if (i < N_NODES) {
        int o = g_off[i] + g_bsum[i >> 10];
        g_off[i] = o;
        g_cur[i] = o;
    }
}
__global__ void k_fill_csr(const int* __restrict__ src, const int* __restrict__ dst) {
    int e = blockIdx.x * blockDim.x + threadIdx.x;
    if (e < N_EDGES) {
        int pos = atomicAdd(&g_cur[dst[e]], 1);
        g_csr[pos] = src[e];
    }
}

// ---------------- 3xTF32 mma.sync GEMM (R11-proven: 256 thr, 32x64 warp tile)
template<int K>
__global__ void __launch_bounds__(256) k_mma_gemm(
    const float* __restrict__ A, const float* __restrict__ Bg,
    float* __restrict__ T, float* __restrict__ S) {
    extern __shared__ float sm[];
    float* As = sm;                    // [2][128][36]
    float* Bs = sm + 2 * A_PL;         // [2][32][136]
    const int tid = threadIdx.x, lane = tid & 31, wid = tid >> 5;
    const int m0 = blockIdx.x * 128;
    const int warp_m = (wid & 3) * 32;
    const int warp_n = (wid >> 2) * 64;
    const int gi = lane >> 2, ti = lane & 3;

    float acc[2][8][4];
#pragma unroll
    for (int mt = 0; mt < 2; ++mt)
#pragma unroll
        for (int nt = 0; nt < 8; ++nt)
#pragma unroll
            for (int c = 0; c < 4; ++c) acc[mt][nt][c] = 0.f;

    for (int k0 = 0; k0 < K; k0 += 32) {
#pragma unroll
        for (int it = 0; it < 4; ++it) {
            int idx = it * 256 + tid;
            int row = idx >> 3, kq = (idx & 7) << 2;
            int grow = m0 + row;
            float4 v = (grow < N_NODES)
                ? *reinterpret_cast<const float4*>(A + (size_t)grow * K + k0 + kq)
                : make_float4(0.f, 0.f, 0.f, 0.f);
            uint32_t h1[4], h2[4];
            split_tf32(v.x, h1[0], h2[0]);
            split_tf32(v.y, h1[1], h2[1]);
            split_tf32(v.z, h1[2], h2[2]);
            split_tf32(v.w, h1[3], h2[3]);
            float* p0 = As + row * 36 + kq;
            *reinterpret_cast<float4*>(p0) = make_float4(
                __uint_as_float(h1[0]), __uint_as_float(h1[1]),
                __uint_as_float(h1[2]), __uint_as_float(h1[3]));
            *reinterpret_cast<float4*>(p0 + A_PL) = make_float4(
                __uint_as_float(h2[0]), __uint_as_float(h2[1]),
                __uint_as_float(h2[2]), __uint_as_float(h2[3]));
        }
#pragma unroll
        for (int it = 0; it < 8; ++it) {
            int idx = it * 256 + tid;
            int pl = idx >> 10, rem = idx & 1023;
            int kk = rem >> 5, nq = (rem & 31) << 2;
            float4 v = *reinterpret_cast<const float4*>(
                Bg + (size_t)pl * (K * 128) + (size_t)(k0 + kk) * 128 + nq);
            *reinterpret_cast<float4*>(Bs + pl * B_PL + kk * 136 + nq) = v;
        }
        __syncthreads();

#pragma unroll
        for (int ks = 0; ks < 4; ++ks) {
            uint32_t af[2][2][4];
#pragma unroll
            for (int mt = 0; mt < 2; ++mt)
#pragma unroll
                for (int pl = 0; pl < 2; ++pl) {
                    const float* b = As + pl * A_PL + (warp_m + mt * 16 + gi) * 36 + ks * 8 + ti;
                    af[mt][pl][0] = __float_as_uint(b[0]);
                    af[mt][pl][1] = __float_as_uint(b[8 * 36]);
                    af[mt][pl][2] = __float_as_uint(b[4]);
                    af[mt][pl][3] = __float_as_uint(b[8 * 36 + 4]);
                }
            uint32_t bf[8][2][2];
#pragma unroll
            for (int nt = 0; nt < 8; ++nt)
#pragma unroll
                for (int pl = 0; pl < 2; ++pl) {
                    const float* b = Bs + pl * B_PL + (ks * 8 + ti) * 136 + warp_n + nt * 8 + gi;
                    bf[nt][pl][0] = __float_as_uint(b[0]);
                    bf[nt][pl][1] = __float_as_uint(b[4 * 136]);
                }
#pragma unroll
            for (int mt = 0; mt < 2; ++mt)
#pragma unroll
                for (int nt = 0; nt < 8; ++nt) {
                    MMA_TF32(acc[mt][nt], af[mt][1], bf[nt][0]);   // A2*B1
                    MMA_TF32(acc[mt][nt], af[mt][0], bf[nt][1]);   // A1*B2
                    MMA_TF32(acc[mt][nt], af[mt][0], bf[nt][0]);   // A1*B1
                }
        }
        __syncthreads();
    }

    float* O = warp_n ? S : T;
#pragma unroll
    for (int mt = 0; mt < 2; ++mt) {
        int row0 = m0 + warp_m + mt * 16 + gi;
#pragma unroll
        for (int nt = 0; nt < 8; ++nt) {
            int col = nt * 8 + 2 * ti;
            if (row0 < N_NODES)
                *reinterpret_cast<float2*>(O + (size_t)row0 * 64 + col) =
                    make_float2(acc[mt][nt][0], acc[mt][nt][1]);
            if (row0 + 8 < N_NODES)
                *reinterpret_cast<float2*>(O + (size_t)(row0 + 8) * 64 + col) =
                    make_float2(acc[mt][nt][2], acc[mt][nt][3]);
        }
    }
}

// ---------------- aggregate + epilogue: 8-deep load pipeline ------------
// out[n,:] = relu( mean_{j->n} T[j,:] + S[n,:] + bias )
// Prefetch 8 CSR indices, issue 8 independent row loads (MLP=8/lane), then
// reduce in the SAME sequential order as before (bit-identical result).
__global__ void __launch_bounds__(256) k_aggfuse(
    const float* __restrict__ T, const float* __restrict__ S,
    const float* __restrict__ bias, float* __restrict__ out) {
    int node = (blockIdx.x * blockDim.x + threadIdx.x) >> 5;
    int lane = threadIdx.x & 31;
    if (node >= N_NODES) return;
    int beg = g_off[node];
    int d   = g_deg[node];
    int end = beg + d;
    float2 acc = make_float2(0.f, 0.f);
    int e = beg;
    for (; e + 8 <= end; e += 8) {
        int s[8];
#pragma unroll
        for (int j = 0; j < 8; ++j) s[j] = g_csr[e + j];
        float2 v[8];
#pragma unroll
        for (int j = 0; j < 8; ++j)
            v[j] = *reinterpret_cast<const float2*>(T + (size_t)s[j] * 64 + 2 * lane);
#pragma unroll
        for (int j = 0; j < 8; ++j) { acc.x += v[j].x; acc.y += v[j].y; }
    }
    for (; e < end; ++e) {
        float2 v = *reinterpret_cast<const float2*>(T + (size_t)g_csr[e] * 64 + 2 * lane);
        acc.x += v.x; acc.y += v.y;
    }
    float inv = 1.f / (float)(d > 0 ? d : 1);
    float2 sv = *reinterpret_cast<const float2*>(S + (size_t)node * 64 + 2 * lane);
    float2 bv = *reinterpret_cast<const float2*>(bias + 2 * lane);
    float2 r;
    r.x = acc.x * inv + sv.x + bv.x;  r.x = r.x > 0.f ? r.x : 0.f;
    r.y = acc.y * inv + sv.y + bv.y;  r.y = r.y > 0.f ? r.y : 0.f;
    *reinterpret_cast<float2*>(out + (size_t)node * 64 + 2 * lane) = r;
}

// ---------------- sort-pool (R11-proven) --------------------------------
__global__ void __launch_bounds__(128) k_sortpool(const float* __restrict__ h) {
    int g = blockIdx.x;
    __shared__ float key[PER_G];
    __shared__ int   sel[TOPK];
    int t = threadIdx.x;
    if (t < PER_G) key[t] = h[((size_t)(g * PER_G + t)) * HID + (HID - 1)];
    __syncthreads();
    if (t < PER_G) {
        float ki = key[t];
        int r = 0;
#pragma unroll 4
        for (int j = 0; j < PER_G; ++j) {
            float kj = key[j];
            r += (kj > ki) || (kj == ki && j < t);
        }
        if (r < TOPK) sel[r] = t;
    }
    __syncthreads();
    for (int idx = t; idx < TOPK * HID; idx += 128) {
        int slot = idx >> 6, f = idx & 63;
        g_topk[(size_t)g * (TOPK * HID) + idx] =
            h[((size_t)(g * PER_G + sel[slot])) * HID + f];
    }
}

// ---------------- conv1d + MLP head: 4 graphs per block -----------------
__global__ void __launch_bounds__(256) k_head(
    const float* __restrict__ cw, const float* __restrict__ cb,
    const float* __restrict__ w1, const float* __restrict__ bb1,
    const float* __restrict__ w2, const float* __restrict__ bb2,
    float* __restrict__ out) {
    int g0 = blockIdx.x * G_PER_BLK, tid = threadIdx.x;
    __shared__ float cws[CONV_O * HID * KSZ];
    __shared__ float tk[G_PER_BLK][TOPK * HID];
    __shared__ float yf[G_PER_BLK][FLAT];
    __shared__ float z[G_PER_BLK][HID];

    for (int i = tid; i < CONV_O * HID * KSZ; i += 256) cws[i] = cw[i];
    for (int i = tid; i < G_PER_BLK * TOPK * HID; i += 256) {
        int gl = i / (TOPK * HID), r = i % (TOPK * HID);
        tk[gl][r] = g_topk[(size_t)(g0 + gl) * (TOPK * HID) + r];
    }
    __syncthreads();

    for (int idx = tid; idx < G_PER_BLK * FLAT; idx += 256) {
        int gl = idx / FLAT, rem = idx % FLAT;
        int o = rem / CONV_T, t = rem % CONV_T;
        float acc = __ldg(cb + o);
        const float* cwo = cws + o * (HID * KSZ);
#pragma unroll 8
        for (int i = 0; i < HID; ++i) {
            const float* cwp = cwo + i * KSZ;
            acc += tk[gl][(t + 0) * HID + i] * cwp[0];
            acc += tk[gl][(t + 1) * HID + i] * cwp[1];
            acc += tk[gl][(t + 2) * HID + i] * cwp[2];
        }
        yf[gl][rem] = acc > 0.f ? acc : 0.f;
    }
    __syncthreads();

    {
        int gl = tid >> 6, hh = tid & 63;
        float acc = 0.f;
        for (int f = 0; f < FLAT; ++f)
            acc += yf[gl][f] * __ldg(w1 + (size_t)f * 64 + hh);
        float v = acc + __ldg(bb1 + hh);
        z[gl][hh] = v > 0.f ? v : 0.f;
    }
    __syncthreads();

    if (tid < G_PER_BLK) {
        float s = __ldg(bb2);
#pragma unroll
        for (int h = 0; h < HID; ++h) s += z[tid][h] * __ldg(w2 + h);
        out[g0 + tid] = s;
    }
}

// ---------------- launch ------------------------------------------------
extern "C" void kernel_launch(void* const* d_in, const int* in_sizes, int n_in,
                              void* d_out, int out_size) {
    const float* x   = (const float*)d_in[0];
    const int*   src = (const int*)d_in[1];
    const int*   dst = (const int*)d_in[2];
    const float* wl1 = (const float*)d_in[4];
    const float* wr1 = (const float*)d_in[5];
    const float* b1  = (const float*)d_in[6];
    const float* wl2 = (const float*)d_in[7];
    const float* wr2 = (const float*)d_in[8];
    const float* b2  = (const float*)d_in[9];
    const float* wl3 = (const float*)d_in[10];
    const float* wr3 = (const float*)d_in[11];
    const float* b3  = (const float*)d_in[12];
    const float* cw  = (const float*)d_in[13];
    const float* cb  = (const float*)d_in[14];
    const float* w1  = (const float*)d_in[15];
    const float* bb1 = (const float*)d_in[16];
    const float* w2  = (const float*)d_in[17];
    const float* bb2 = (const float*)d_in[18];
    float* out = (float*)d_out;

    float *p_TS, *p_h, *p_W;
    cudaGetSymbolAddress((void**)&p_TS, g_TS);
    cudaGetSymbolAddress((void**)&p_h,  g_h);
    cudaGetSymbolAddress((void**)&p_W,  g_Bimg);
    float* p_T = p_TS;
    float* p_S = p_TS + (size_t)N_NODES * 64;

    const int GEMM_SZ = GEMM_FLOATS * 4;   // 71680
    cudaFuncSetAttribute(k_mma_gemm<128>, cudaFuncAttributeMaxDynamicSharedMemorySize, GEMM_SZ);
    cudaFuncSetAttribute(k_mma_gemm<64>,  cudaFuncAttributeMaxDynamicSharedMemorySize, GEMM_SZ);

    const int aggBlocks = (N_NODES * 32 + 255) / 256;

    // 0: init   1: count   2: scan1
    k_init<<<(N_NODES + 255) / 256, 256>>>(wl1, wr1, wl2, wr2, wl3, wr3);
    k_count<<<(N_EDGES + 255) / 256, 256>>>(dst);
    k_scan1<<<NB_SCAN, SCAN_B>>>();
    // 3: layer-1 GEMM (256-thr) — profiled by the ncu window next round
    k_mma_gemm<128><<<M_TILES, 256, GEMM_SZ>>>(x, p_W, p_T, p_S);
    // 4-6: finish CSR
    k_scan2<<<1, 32>>>();
    k_scan3<<<(N_NODES + 255) / 256, 256>>>();
    k_fill_csr<<<(N_EDGES + 255) / 256, 256>>>(src, dst);
    // 7: agg1   8: gemm2   9: agg2   10: gemm3   11: agg3
    k_aggfuse<<<aggBlocks, 256>>>(p_T, p_S, b1, p_h);
    k_mma_gemm<64><<<M_TILES, 256, GEMM_SZ>>>(p_h, p_W + 32768, p_T, p_S);
    k_aggfuse<<<aggBlocks, 256>>>(p_T, p_S, b2, p_h);
    k_mma_gemm<64><<<M_TILES, 256, GEMM_SZ>>>(p_h, p_W + 49152, p_T, p_S);
    k_aggfuse<<<aggBlocks, 256>>>(p_T, p_S, b3, p_h);
    // 12: sort-pool   13: head
    k_sortpool<<<N_GRAPHS, 128>>>(p_h);
    k_head<<<N_GRAPHS / G_PER_BLK, 256>>>(cw, cb, w1, bb1, w2, bb2, out);
}